// round 10
// baseline (speedup 1.0000x reference)
#include <cuda_runtime.h>
#include <stdint.h>

// MaxUnpooling2D, pool 2x2, scatter-add:
//   updates: [16,128,128,64] f32, mask: same shape int32 (flat idx into OH*OW*C)
//   out:     [16,256,256,64] f32
//
// dst = (b << 22) + (mask & ~63) + c      (C=64, OH*OW*C = 1<<22, H*W*C = 1<<20)
//
// Phased (2 batches/phase) so the 33.5 MB output window is L2-resident; the
// fused kernel block-specializes: 2048 blocks scatter phase p (now with
// red.global.add.v4.f32 — one 16B vector reduction per 4-channel group),
// 2048 blocks stream-zero phase p+1's window.

#define BATCHES         16u
#define IN_PER_BATCH    (1u << 20)          // 128*128*64
#define OUT_PER_BATCH   (1u << 22)          // 256*256*64
#define BATCH_PER_PHASE 2u
#define PHASES          (BATCHES / BATCH_PER_PHASE)   // 8

#define SCAT_BLOCKS     2048u               // 2048*256 threads * 4 elems = 2.1M
#define ZERO_BLOCKS     2048u               // 2048*256 threads * 4 float4 = 33.5MB
#define ZERO_T          (ZERO_BLOCKS * 256u)

__device__ __forceinline__ void red_add_v4(float* addr, float4 v) {
    asm volatile("red.global.add.v4.f32 [%0], {%1, %2, %3, %4};"
                 :: "l"(addr), "f"(v.x), "f"(v.y), "f"(v.z), "f"(v.w)
                 : "memory");
}

__global__ void __launch_bounds__(256) unpool_zero_kernel(float4* __restrict__ out) {
    unsigned t = blockIdx.x * 256u + threadIdx.x;
    float4 z = make_float4(0.f, 0.f, 0.f, 0.f);
    out[t]               = z;
    out[t +      ZERO_T] = z;
    out[t + 2u * ZERO_T] = z;
    out[t + 3u * ZERO_T] = z;
}

__global__ void __launch_bounds__(256) unpool_fused_kernel(
        const float4* __restrict__ upd,
        const int4*   __restrict__ msk,
        float*        __restrict__ out,
        unsigned      group_base,         // first float4-group of this phase
        float4*       __restrict__ zwin,  // next phase's window
        int           do_zero) {
    if (blockIdx.x < SCAT_BLOCKS) {
        // ---- scatter phase p ----
        unsigned g = group_base + blockIdx.x * 256u + threadIdx.x;
        float4 u = upd[g];
        int4   m = msk[g];

        unsigned e      = g << 2;            // first element index of the group
        unsigned base_b = (e >> 20) << 22;   // batch offset in output
        unsigned c      = e & 63u;           // channel (multiple of 4)

        float* ob = out + base_b + c;

        // Common fast path: all four masks share the same pooled cell
        // (same 64-float block) -> one 16B vector reduction.
        unsigned bx = (unsigned)m.x & ~63u;
        if (((unsigned)m.y & ~63u) == bx &&
            ((unsigned)m.z & ~63u) == bx &&
            ((unsigned)m.w & ~63u) == bx) {
            red_add_v4(ob + bx, u);
        } else {
            atomicAdd(ob + bx + 0u, u.x);
            atomicAdd(ob + ((unsigned)m.y & ~63u) + 1u, u.y);
            atomicAdd(ob + ((unsigned)m.z & ~63u) + 2u, u.z);
            atomicAdd(ob + ((unsigned)m.w & ~63u) + 3u, u.w);
        }
    } else if (do_zero) {
        // ---- zero window p+1 ----
        unsigned t = (blockIdx.x - SCAT_BLOCKS) * 256u + threadIdx.x;
        float4 z = make_float4(0.f, 0.f, 0.f, 0.f);
        zwin[t]               = z;
        zwin[t +      ZERO_T] = z;
        zwin[t + 2u * ZERO_T] = z;
        zwin[t + 3u * ZERO_T] = z;
    }
}

extern "C" void kernel_launch(void* const* d_in, const int* in_sizes, int n_in,
                              void* d_out, int out_size) {
    const float4* upd = (const float4*)d_in[0];
    const int4*   msk = (const int4*)d_in[1];
    float*        out = (float*)d_out;

    const unsigned groups_per_phase = BATCH_PER_PHASE * IN_PER_BATCH / 4u; // 524,288
    const size_t   win_elems        = (size_t)BATCH_PER_PHASE * OUT_PER_BATCH;

    // Prologue: zero window 0
    unpool_zero_kernel<<<ZERO_BLOCKS, 256u>>>((float4*)out);

    for (unsigned p = 0; p < PHASES; p++) {
        int do_zero = (p + 1u < PHASES);
        float4* zwin = (float4*)(out + (size_t)(p + 1u) * win_elems * (do_zero ? 1 : 0));
        unpool_fused_kernel<<<SCAT_BLOCKS + ZERO_BLOCKS, 256u>>>(
            upd, msk, out, p * groups_per_phase, zwin, do_zero);
    }
}

// round 13
// speedup vs baseline: 1.0071x; 1.0071x over previous
#include <cuda_runtime.h>
#include <stdint.h>

// MaxUnpooling2D, pool 2x2, scatter-add:
//   updates: [16,128,128,64] f32, mask: same shape int32 (flat idx into OH*OW*C)
//   out:     [16,256,256,64] f32
//
// dst = (b << 22) + (mask & ~63) + c      (C=64, OH*OW*C = 1<<22, H*W*C = 1<<20)
//
// Phased (2 batches/phase) so the 33.5 MB output window is L2-resident; the
// fused kernel block-specializes: 2048 blocks scatter phase p (now with
// red.global.add.v4.f32 — one 16B vector reduction per 4-channel group),
// 2048 blocks stream-zero phase p+1's window.

#define BATCHES         16u
#define IN_PER_BATCH    (1u << 20)          // 128*128*64
#define OUT_PER_BATCH   (1u << 22)          // 256*256*64
#define BATCH_PER_PHASE 2u
#define PHASES          (BATCHES / BATCH_PER_PHASE)   // 8

#define SCAT_BLOCKS     2048u               // 2048*256 threads * 4 elems = 2.1M
#define ZERO_BLOCKS     2048u               // 2048*256 threads * 4 float4 = 33.5MB
#define ZERO_T          (ZERO_BLOCKS * 256u)

__device__ __forceinline__ void red_add_v4(float* addr, float4 v) {
    asm volatile("red.global.add.v4.f32 [%0], {%1, %2, %3, %4};"
                 :: "l"(addr), "f"(v.x), "f"(v.y), "f"(v.z), "f"(v.w)
                 : "memory");
}

__global__ void __launch_bounds__(256) unpool_zero_kernel(float4* __restrict__ out) {
    unsigned t = blockIdx.x * 256u + threadIdx.x;
    float4 z = make_float4(0.f, 0.f, 0.f, 0.f);
    out[t]               = z;
    out[t +      ZERO_T] = z;
    out[t + 2u * ZERO_T] = z;
    out[t + 3u * ZERO_T] = z;
}

__global__ void __launch_bounds__(256) unpool_fused_kernel(
        const float4* __restrict__ upd,
        const int4*   __restrict__ msk,
        float*        __restrict__ out,
        unsigned      group_base,         // first float4-group of this phase
        float4*       __restrict__ zwin,  // next phase's window
        int           do_zero) {
    if (blockIdx.x < SCAT_BLOCKS) {
        // ---- scatter phase p ----
        unsigned g = group_base + blockIdx.x * 256u + threadIdx.x;
        float4 u = upd[g];
        int4   m = msk[g];

        unsigned e      = g << 2;            // first element index of the group
        unsigned base_b = (e >> 20) << 22;   // batch offset in output
        unsigned c      = e & 63u;           // channel (multiple of 4)

        float* ob = out + base_b + c;

        // Common fast path: all four masks share the same pooled cell
        // (same 64-float block) -> one 16B vector reduction.
        unsigned bx = (unsigned)m.x & ~63u;
        if (((unsigned)m.y & ~63u) == bx &&
            ((unsigned)m.z & ~63u) == bx &&
            ((unsigned)m.w & ~63u) == bx) {
            red_add_v4(ob + bx, u);
        } else {
            atomicAdd(ob + bx + 0u, u.x);
            atomicAdd(ob + ((unsigned)m.y & ~63u) + 1u, u.y);
            atomicAdd(ob + ((unsigned)m.z & ~63u) + 2u, u.z);
            atomicAdd(ob + ((unsigned)m.w & ~63u) + 3u, u.w);
        }
    } else if (do_zero) {
        // ---- zero window p+1 ----
        unsigned t = (blockIdx.x - SCAT_BLOCKS) * 256u + threadIdx.x;
        float4 z = make_float4(0.f, 0.f, 0.f, 0.f);
        zwin[t]               = z;
        zwin[t +      ZERO_T] = z;
        zwin[t + 2u * ZERO_T] = z;
        zwin[t + 3u * ZERO_T] = z;
    }
}

extern "C" void kernel_launch(void* const* d_in, const int* in_sizes, int n_in,
                              void* d_out, int out_size) {
    const float4* upd = (const float4*)d_in[0];
    const int4*   msk = (const int4*)d_in[1];
    float*        out = (float*)d_out;

    const unsigned groups_per_phase = BATCH_PER_PHASE * IN_PER_BATCH / 4u; // 524,288
    const size_t   win_elems        = (size_t)BATCH_PER_PHASE * OUT_PER_BATCH;

    // Prologue: zero window 0
    unpool_zero_kernel<<<ZERO_BLOCKS, 256u>>>((float4*)out);

    for (unsigned p = 0; p < PHASES; p++) {
        int do_zero = (p + 1u < PHASES);
        float4* zwin = (float4*)(out + (size_t)(p + 1u) * win_elems * (do_zero ? 1 : 0));
        unpool_fused_kernel<<<SCAT_BLOCKS + ZERO_BLOCKS, 256u>>>(
            upd, msk, out, p * groups_per_phase, zwin, do_zero);
    }
}